// round 2
// baseline (speedup 1.0000x reference)
#include <cuda_runtime.h>
#include <cuda_fp16.h>

#define N_CAP 100000
#define E_CAP 1600000
#define F_DIM 128

// -------- static scratch (allocation-free rule) --------
__device__ uint2 g_xh [(size_t)N_CAP * 32];   // x  in fp16, 4 halves per uint2 (25.6 MB)
__device__ uint2 g_h1h[(size_t)N_CAP * 32];   // h1 in fp16 (25.6 MB)
__device__ float g_dinv[N_CAP];
__device__ int   g_rowptr[N_CAP + 1];
__device__ int   g_cnt[N_CAP];                // histogram -> exclusive prefix -> cursor
__device__ int2  g_cw[E_CAP];                 // (src, bitcast(dinv[src])) sorted by dst
__device__ int   g_bsums[1024];
__device__ int   g_is64;

// -------- 1) prep: convert x->fp16, zero histogram, detect edge dtype --------
__global__ void prep_k(const float2* __restrict__ x, const void* ei, int N, int NF2) {
    int idx = blockIdx.x * blockDim.x + threadIdx.x;
    // dtype detect (warp 0 of block 0): int64 values must be in [0, 2^31)
    if (blockIdx.x == 0 && threadIdx.x < 32) {
        const long long* el = (const long long*)ei;
        int ok = 1;
        #pragma unroll
        for (int i = threadIdx.x; i < 128; i += 32) {
            long long v = el[i];
            if (v < 0 || v >= (1LL << 31)) ok = 0;
        }
        ok = __all_sync(0xffffffffu, ok);
        if (threadIdx.x == 0) g_is64 = ok;
    }
    if (idx < N) g_cnt[idx] = 0;
    // convert pairs of floats -> half2 (NF2 = N*F/2)
    for (int i = idx; i < NF2; i += gridDim.x * blockDim.x) {
        float2 v = x[i];
        ((__half2*)g_xh)[i] = __floats2half2_rn(v.x, v.y);
    }
}

// -------- 2) histogram of dst --------
__global__ void hist_k(const void* ei, int E) {
    int e = blockIdx.x * blockDim.x + threadIdx.x;
    if (e >= E) return;
    int dst;
    if (g_is64) dst = (int)((const long long*)ei)[(size_t)E + e];
    else        dst = ((const int*)ei)[(size_t)E + e];
    atomicAdd(&g_cnt[dst], 1);
}

// -------- 3) per-1024-chunk totals --------
__global__ void scan1_k(int N) {
    __shared__ int sh[256];
    int base = blockIdx.x * 1024;
    int tid  = threadIdx.x;
    int s = 0;
    #pragma unroll
    for (int k = 0; k < 4; k++) {
        int i = base + tid + k * 256;
        if (i < N) s += g_cnt[i];
    }
    sh[tid] = s; __syncthreads();
    for (int off = 128; off > 0; off >>= 1) {
        if (tid < off) sh[tid] += sh[tid + off];
        __syncthreads();
    }
    if (tid == 0) g_bsums[blockIdx.x] = sh[0];
}

// -------- 4) fused: block-prefix + local scan + dinv + cursor + rowptr --------
__global__ void scan3_k(int N) {
    __shared__ int sh[1024];
    __shared__ int bpref;
    int tid = threadIdx.x, bid = blockIdx.x;
    if (tid < 32) {
        int s = 0;
        for (int b = tid; b < bid; b += 32) s += g_bsums[b];
        #pragma unroll
        for (int o = 16; o > 0; o >>= 1) s += __shfl_xor_sync(0xffffffffu, s, o);
        if (tid == 0) bpref = s;
    }
    int i   = bid * 1024 + tid;
    int own = (i < N) ? g_cnt[i] : 0;
    sh[tid] = own; __syncthreads();
    for (int off = 1; off < 1024; off <<= 1) {
        int v = (tid >= off) ? sh[tid - off] : 0;
        __syncthreads();
        sh[tid] += v;
        __syncthreads();
    }
    if (i < N) {
        int excl = bpref + sh[tid] - own;
        g_rowptr[i] = excl;
        g_cnt[i]    = excl;                          // scatter cursor
        g_dinv[i]   = rsqrtf((float)own + 1.0f);
        if (i == N - 1) g_rowptr[N] = excl + own;
    }
}

// -------- 5) scatter edges into CSR with precomputed source weight --------
__global__ void scatter_k(const void* ei, int E) {
    int e = blockIdx.x * blockDim.x + threadIdx.x;
    if (e >= E) return;
    int src, dst;
    if (g_is64) {
        src = (int)((const long long*)ei)[e];
        dst = (int)((const long long*)ei)[(size_t)E + e];
    } else {
        src = ((const int*)ei)[e];
        dst = ((const int*)ei)[(size_t)E + e];
    }
    int pos = atomicAdd(&g_cnt[dst], 1);
    g_cw[pos] = make_int2(src, __float_as_int(g_dinv[src]));
}

// -------- gather-accumulate core: fp16 rows, fp32 accumulation --------
__device__ __forceinline__ void accum_row(float4& acc, const uint2* __restrict__ tab,
                                          int s, float w) {
    uint2 v = tab[(size_t)s * 32 + (threadIdx.x & 31)];
    float2 a = __half22float2(*(const __half2*)&v.x);
    float2 b = __half22float2(*(const __half2*)&v.y);
    acc.x = fmaf(w, a.x, acc.x);
    acc.y = fmaf(w, a.y, acc.y);
    acc.z = fmaf(w, b.x, acc.z);
    acc.w = fmaf(w, b.y, acc.w);
}

__device__ __forceinline__ float4 hop_row(const uint2* __restrict__ tab, int gw, int lane) {
    int beg = g_rowptr[gw], end = g_rowptr[gw + 1];
    float4 acc = make_float4(0.f, 0.f, 0.f, 0.f);
    for (int j = beg; j < end; j += 32) {
        int2 cw = make_int2(0, 0);
        if (j + lane < end) cw = g_cw[j + lane];
        int cnt = min(32, end - j);
        int k = 0;
        for (; k + 1 < cnt; k += 2) {
            int   s0 = __shfl_sync(0xffffffffu, cw.x, k);
            float w0 = __int_as_float(__shfl_sync(0xffffffffu, cw.y, k));
            int   s1 = __shfl_sync(0xffffffffu, cw.x, k + 1);
            float w1 = __int_as_float(__shfl_sync(0xffffffffu, cw.y, k + 1));
            uint2 v0 = tab[(size_t)s0 * 32 + lane];
            uint2 v1 = tab[(size_t)s1 * 32 + lane];
            float2 a0 = __half22float2(*(const __half2*)&v0.x);
            float2 b0 = __half22float2(*(const __half2*)&v0.y);
            float2 a1 = __half22float2(*(const __half2*)&v1.x);
            float2 b1 = __half22float2(*(const __half2*)&v1.y);
            acc.x = fmaf(w0, a0.x, fmaf(w1, a1.x, acc.x));
            acc.y = fmaf(w0, a0.y, fmaf(w1, a1.y, acc.y));
            acc.z = fmaf(w0, b0.x, fmaf(w1, b1.x, acc.z));
            acc.w = fmaf(w0, b0.y, fmaf(w1, b1.y, acc.w));
        }
        if (k < cnt) {
            int   s0 = __shfl_sync(0xffffffffu, cw.x, k);
            float w0 = __int_as_float(__shfl_sync(0xffffffffu, cw.y, k));
            accum_row(acc, tab, s0, w0);
        }
    }
    // self loop: dinv^2 * own row
    float di = g_dinv[gw];
    uint2 v  = tab[(size_t)gw * 32 + lane];
    float2 a = __half22float2(*(const __half2*)&v.x);
    float2 b = __half22float2(*(const __half2*)&v.y);
    float sl = di * di;
    acc.x = di * acc.x + sl * a.x;
    acc.y = di * acc.y + sl * a.y;
    acc.z = di * acc.z + sl * b.x;
    acc.w = di * acc.w + sl * b.y;
    return acc;
}

// -------- 6) hop 1 (x_fp16 -> h1_fp16) --------
__global__ void hop1_k(int N) {
    int gw   = (blockIdx.x * blockDim.x + threadIdx.x) >> 5;
    int lane = threadIdx.x & 31;
    if (gw >= N) return;
    float4 acc = hop_row(g_xh, gw, lane);
    uint2 o;
    *(__half2*)&o.x = __floats2half2_rn(acc.x, acc.y);
    *(__half2*)&o.y = __floats2half2_rn(acc.z, acc.w);
    g_h1h[(size_t)gw * 32 + lane] = o;
}

// -------- 7) hop 2 fused with linear projection --------
__global__ void hop2_gemm_k(const float* __restrict__ W, const float* __restrict__ b,
                            float* __restrict__ out, int N, int C) {
    extern __shared__ float sm[];               // C*F + C floats
    const float4* sW4 = (const float4*)sm;
    float*        sb  = sm + C * F_DIM;
    for (int idx = threadIdx.x; idx < C * F_DIM; idx += blockDim.x) sm[idx] = W[idx];
    for (int idx = threadIdx.x; idx < C; idx += blockDim.x) sb[idx] = b[idx];
    __syncthreads();

    int gw   = (blockIdx.x * blockDim.x + threadIdx.x) >> 5;
    int lane = threadIdx.x & 31;
    if (gw >= N) return;

    float4 acc = hop_row(g_h1h, gw, lane);      // h2 row segment [lane*4 .. lane*4+3]

    float my0 = 0.f, my1 = 0.f;
    #pragma unroll 8
    for (int c = 0; c < C; c++) {
        float4 wv = sW4[c * 32 + lane];
        float p = acc.x * wv.x + acc.y * wv.y + acc.z * wv.z + acc.w * wv.w;
        p += __shfl_xor_sync(0xffffffffu, p, 16);
        p += __shfl_xor_sync(0xffffffffu, p, 8);
        p += __shfl_xor_sync(0xffffffffu, p, 4);
        p += __shfl_xor_sync(0xffffffffu, p, 2);
        p += __shfl_xor_sync(0xffffffffu, p, 1);
        p += sb[c];
        if (c < 32) { if (lane == c)        my0 = p; }
        else        { if (lane == c - 32)   my1 = p; }
    }
    float* orow = out + (size_t)gw * C;
    orow[lane] = my0;                            // c = 0..31
    if (lane < C - 32) orow[32 + lane] = my1;    // c = 32..39
}

extern "C" void kernel_launch(void* const* d_in, const int* in_sizes, int n_in,
                              void* d_out, int out_size) {
    const float* x  = (const float*)d_in[0];
    const void*  ei = d_in[1];
    const float* W  = (const float*)d_in[2];
    const float* b  = (const float*)d_in[3];

    int C  = in_sizes[3];                 // 40
    int F  = in_sizes[2] / C;             // 128
    int N  = in_sizes[0] / F;             // 100000
    int E  = in_sizes[1] / 2;             // 1600000
    int NB = (N + 1023) / 1024;
    int NF2 = N * F / 2;

    prep_k<<<592, 256>>>((const float2*)x, ei, N, NF2);          // 1
    hist_k<<<(E + 255) / 256, 256>>>(ei, E);                     // 2
    scan1_k<<<NB, 256>>>(N);                                     // 3
    scan3_k<<<NB, 1024>>>(N);                                    // 4
    scatter_k<<<(E + 255) / 256, 256>>>(ei, E);                  // 5
    hop1_k<<<(N * 32 + 255) / 256, 256>>>(N);                    // 6  (ncu -s 5 lands here)
    size_t shmem = (size_t)(C * F + C) * sizeof(float);
    hop2_gemm_k<<<(N * 32 + 1023) / 1024, 1024, shmem>>>(W, b, (float*)d_out, N, C);
}

// round 4
// speedup vs baseline: 1.6234x; 1.6234x over previous
#include <cuda_runtime.h>

#define N_CAP 100000
#define E_CAP 1600000
#define F_DIM 128

// -------- static scratch (allocation-free rule) --------
__device__ float g_h1[(size_t)N_CAP * F_DIM];   // hop-1 result (51.2 MB)
__device__ float g_dinv[N_CAP];
__device__ int   g_rowptr[N_CAP + 1];
__device__ int   g_cnt[N_CAP];                  // histogram -> cursor
__device__ int2  g_cw[E_CAP];                   // (src, bitcast(dinv[src])) sorted by dst
__device__ int   g_bsums[1024];
__device__ int   g_is64;

// -------- 1) prep: zero histogram + parallel dtype detect --------
__global__ void prep_k(const void* ei, int N) {
    if (blockIdx.x == 0 && threadIdx.x < 32) {
        const long long* el = (const long long*)ei;
        int ok = 1;
        #pragma unroll
        for (int i = threadIdx.x; i < 128; i += 32) {
            long long v = el[i];
            if (v < 0 || v >= (1LL << 31)) ok = 0;
        }
        ok = __all_sync(0xffffffffu, ok);
        if (threadIdx.x == 0) g_is64 = ok;
    }
    int idx = blockIdx.x * blockDim.x + threadIdx.x;
    if (idx < N) g_cnt[idx] = 0;
}

// -------- 2) histogram of dst --------
__global__ void hist_k(const void* ei, int E) {
    int e = blockIdx.x * blockDim.x + threadIdx.x;
    if (e >= E) return;
    int dst;
    if (g_is64) dst = (int)((const long long*)ei)[(size_t)E + e];
    else        dst = ((const int*)ei)[(size_t)E + e];
    atomicAdd(&g_cnt[dst], 1);
}

// -------- 3) per-1024-chunk totals --------
__global__ void scan1_k(int N) {
    __shared__ int sh[256];
    int base = blockIdx.x * 1024;
    int tid  = threadIdx.x;
    int s = 0;
    #pragma unroll
    for (int k = 0; k < 4; k++) {
        int i = base + tid + k * 256;
        if (i < N) s += g_cnt[i];
    }
    sh[tid] = s; __syncthreads();
    for (int off = 128; off > 0; off >>= 1) {
        if (tid < off) sh[tid] += sh[tid + off];
        __syncthreads();
    }
    if (tid == 0) g_bsums[blockIdx.x] = sh[0];
}

// -------- 4) fused: block prefix + local scan + rowptr + cursor + dinv --------
__global__ void scan3_k(int N) {
    __shared__ int sh[1024];
    __shared__ int bpref;
    int tid = threadIdx.x, bid = blockIdx.x;
    if (tid < 32) {
        int s = 0;
        for (int b = tid; b < bid; b += 32) s += g_bsums[b];
        #pragma unroll
        for (int o = 16; o > 0; o >>= 1) s += __shfl_xor_sync(0xffffffffu, s, o);
        if (tid == 0) bpref = s;
    }
    int i   = bid * 1024 + tid;
    int own = (i < N) ? g_cnt[i] : 0;
    sh[tid] = own; __syncthreads();
    for (int off = 1; off < 1024; off <<= 1) {
        int v = (tid >= off) ? sh[tid - off] : 0;
        __syncthreads();
        sh[tid] += v;
        __syncthreads();
    }
    if (i < N) {
        int excl = bpref + sh[tid] - own;
        g_rowptr[i] = excl;
        g_cnt[i]    = excl;                       // scatter cursor
        g_dinv[i]   = rsqrtf((float)own + 1.0f);
        if (i == N - 1) g_rowptr[N] = excl + own;
    }
}

// -------- 5) scatter edges into CSR with precomputed source weight --------
__global__ void scatter_k(const void* ei, int E) {
    int e = blockIdx.x * blockDim.x + threadIdx.x;
    if (e >= E) return;
    int src, dst;
    if (g_is64) {
        src = (int)((const long long*)ei)[e];
        dst = (int)((const long long*)ei)[(size_t)E + e];
    } else {
        src = ((const int*)ei)[e];
        dst = ((const int*)ei)[(size_t)E + e];
    }
    int pos = atomicAdd(&g_cnt[dst], 1);
    g_cw[pos] = make_int2(src, __float_as_int(g_dinv[src]));
}

// -------- gather-accumulate core: fp32 rows, warp per node --------
__device__ __forceinline__ float4 hop_row(const float4* __restrict__ tab,
                                          int gw, int lane) {
    int beg = g_rowptr[gw], end = g_rowptr[gw + 1];
    float4 acc = make_float4(0.f, 0.f, 0.f, 0.f);
    for (int j = beg; j < end; j += 32) {
        int2 cw = make_int2(0, 0);
        if (j + lane < end) cw = g_cw[j + lane];
        int cnt = min(32, end - j);
        int k = 0;
        for (; k + 1 < cnt; k += 2) {
            int   s0 = __shfl_sync(0xffffffffu, cw.x, k);
            float w0 = __int_as_float(__shfl_sync(0xffffffffu, cw.y, k));
            int   s1 = __shfl_sync(0xffffffffu, cw.x, k + 1);
            float w1 = __int_as_float(__shfl_sync(0xffffffffu, cw.y, k + 1));
            float4 v0 = tab[(size_t)s0 * 32 + lane];
            float4 v1 = tab[(size_t)s1 * 32 + lane];
            acc.x = fmaf(w0, v0.x, fmaf(w1, v1.x, acc.x));
            acc.y = fmaf(w0, v0.y, fmaf(w1, v1.y, acc.y));
            acc.z = fmaf(w0, v0.z, fmaf(w1, v1.z, acc.z));
            acc.w = fmaf(w0, v0.w, fmaf(w1, v1.w, acc.w));
        }
        if (k < cnt) {
            int   s0 = __shfl_sync(0xffffffffu, cw.x, k);
            float w0 = __int_as_float(__shfl_sync(0xffffffffu, cw.y, k));
            float4 v0 = tab[(size_t)s0 * 32 + lane];
            acc.x = fmaf(w0, v0.x, acc.x);
            acc.y = fmaf(w0, v0.y, acc.y);
            acc.z = fmaf(w0, v0.z, acc.z);
            acc.w = fmaf(w0, v0.w, acc.w);
        }
    }
    // self loop: dinv^2 * own row
    float  di = g_dinv[gw];
    float4 v  = tab[(size_t)gw * 32 + lane];
    float  sl = di * di;
    acc.x = di * acc.x + sl * v.x;
    acc.y = di * acc.y + sl * v.y;
    acc.z = di * acc.z + sl * v.z;
    acc.w = di * acc.w + sl * v.w;
    return acc;
}

// -------- 6) hop 1 --------
__global__ void __launch_bounds__(256) hop1_k(const float4* __restrict__ x, int N) {
    int gw   = (blockIdx.x * blockDim.x + threadIdx.x) >> 5;
    int lane = threadIdx.x & 31;
    if (gw >= N) return;
    float4 acc = hop_row(x, gw, lane);
    ((float4*)g_h1)[(size_t)gw * 32 + lane] = acc;
}

// -------- 7) hop 2 fused with linear projection --------
__global__ void __launch_bounds__(256) hop2_gemm_k(const float* __restrict__ W,
                                                   const float* __restrict__ b,
                                                   float* __restrict__ out,
                                                   int N, int C) {
    extern __shared__ float sm[];               // C*F + C floats
    const float4* sW4 = (const float4*)sm;
    float*        sb  = sm + C * F_DIM;
    for (int idx = threadIdx.x; idx < C * F_DIM; idx += blockDim.x) sm[idx] = W[idx];
    for (int idx = threadIdx.x; idx < C; idx += blockDim.x) sb[idx] = b[idx];
    __syncthreads();

    int gw   = (blockIdx.x * blockDim.x + threadIdx.x) >> 5;
    int lane = threadIdx.x & 31;
    if (gw >= N) return;

    float4 acc = hop_row((const float4*)g_h1, gw, lane);

    float my0 = 0.f, my1 = 0.f;
    for (int c = 0; c < C; c++) {
        float4 wv = sW4[c * 32 + lane];
        float p = acc.x * wv.x + acc.y * wv.y + acc.z * wv.z + acc.w * wv.w;
        p += __shfl_xor_sync(0xffffffffu, p, 16);
        p += __shfl_xor_sync(0xffffffffu, p, 8);
        p += __shfl_xor_sync(0xffffffffu, p, 4);
        p += __shfl_xor_sync(0xffffffffu, p, 2);
        p += __shfl_xor_sync(0xffffffffu, p, 1);
        p += sb[c];
        if (c < 32) { if (lane == c)      my0 = p; }
        else        { if (lane == c - 32) my1 = p; }
    }
    float* orow = out + (size_t)gw * C;
    orow[lane] = my0;
    if (lane < C - 32) orow[32 + lane] = my1;
}

extern "C" void kernel_launch(void* const* d_in, const int* in_sizes, int n_in,
                              void* d_out, int out_size) {
    const float* x  = (const float*)d_in[0];
    const void*  ei = d_in[1];
    const float* W  = (const float*)d_in[2];
    const float* b  = (const float*)d_in[3];

    int C  = in_sizes[3];                 // 40
    int F  = in_sizes[2] / C;             // 128
    int N  = in_sizes[0] / F;             // 100000
    int E  = in_sizes[1] / 2;             // 1600000
    int NB = (N + 1023) / 1024;

    prep_k<<<(N + 255) / 256, 256>>>(ei, N);
    hist_k<<<(E + 255) / 256, 256>>>(ei, E);
    scan1_k<<<NB, 256>>>(N);
    scan3_k<<<NB, 1024>>>(N);
    scatter_k<<<(E + 255) / 256, 256>>>(ei, E);

    int blocks = (N * 32 + 255) / 256;    // warp per node
    hop1_k<<<blocks, 256>>>((const float4*)x, N);
    size_t shmem = (size_t)(C * F + C) * sizeof(float);
    hop2_gemm_k<<<blocks, 256, shmem>>>(W, b, (float*)d_out, N, C);
}

// round 6
// speedup vs baseline: 1.7293x; 1.0653x over previous
#include <cuda_runtime.h>
#include <cuda_fp16.h>

#define N_CAP 100000
#define E_CAP 1600000
#define F_DIM 128

// -------- static scratch (allocation-free rule) --------
__device__ uint2 g_xh [(size_t)N_CAP * 32];   // x  rows in fp16 (25.6 MB)
__device__ uint2 g_h1h[(size_t)N_CAP * 32];   // h1 rows in fp16 (25.6 MB)
__device__ float g_dinv[N_CAP];
__device__ int   g_rowptr[N_CAP + 1];
__device__ int   g_cnt[N_CAP];                // histogram -> cursor
__device__ int2  g_cw[E_CAP];                 // (src, bitcast(dinv[src])) sorted by dst
__device__ int   g_bsums[1024];
__device__ int   g_is64;

// -------- 1) prep: zero histogram + parallel dtype detect + x -> fp16 --------
__global__ void prep_k(const float2* __restrict__ x, const void* ei, int N, int NF2) {
    if (blockIdx.x == 0 && threadIdx.x < 32) {
        const long long* el = (const long long*)ei;
        int ok = 1;
        #pragma unroll
        for (int i = threadIdx.x; i < 128; i += 32) {
            long long v = el[i];
            if (v < 0 || v >= (1LL << 31)) ok = 0;
        }
        ok = __all_sync(0xffffffffu, ok);
        if (threadIdx.x == 0) g_is64 = ok;
    }
    int idx    = blockIdx.x * blockDim.x + threadIdx.x;
    int stride = gridDim.x * blockDim.x;
    for (int i = idx; i < N; i += stride) g_cnt[i] = 0;
    for (int i = idx; i < NF2; i += stride) {
        float2 v = x[i];
        ((__half2*)g_xh)[i] = __floats2half2_rn(v.x, v.y);
    }
}

// -------- 2) histogram of dst --------
__global__ void hist_k(const void* ei, int E) {
    int e = blockIdx.x * blockDim.x + threadIdx.x;
    if (e >= E) return;
    int dst;
    if (g_is64) dst = (int)((const long long*)ei)[(size_t)E + e];
    else        dst = ((const int*)ei)[(size_t)E + e];
    atomicAdd(&g_cnt[dst], 1);
}

// -------- 3) per-1024-chunk totals --------
__global__ void scan1_k(int N) {
    __shared__ int sh[256];
    int base = blockIdx.x * 1024;
    int tid  = threadIdx.x;
    int s = 0;
    #pragma unroll
    for (int k = 0; k < 4; k++) {
        int i = base + tid + k * 256;
        if (i < N) s += g_cnt[i];
    }
    sh[tid] = s; __syncthreads();
    for (int off = 128; off > 0; off >>= 1) {
        if (tid < off) sh[tid] += sh[tid + off];
        __syncthreads();
    }
    if (tid == 0) g_bsums[blockIdx.x] = sh[0];
}

// -------- 4) fused: block prefix + local scan + rowptr + cursor + dinv --------
__global__ void scan3_k(int N) {
    __shared__ int sh[1024];
    __shared__ int bpref;
    int tid = threadIdx.x, bid = blockIdx.x;
    if (tid < 32) {
        int s = 0;
        for (int b = tid; b < bid; b += 32) s += g_bsums[b];
        #pragma unroll
        for (int o = 16; o > 0; o >>= 1) s += __shfl_xor_sync(0xffffffffu, s, o);
        if (tid == 0) bpref = s;
    }
    int i   = bid * 1024 + tid;
    int own = (i < N) ? g_cnt[i] : 0;
    sh[tid] = own; __syncthreads();
    for (int off = 1; off < 1024; off <<= 1) {
        int v = (tid >= off) ? sh[tid - off] : 0;
        __syncthreads();
        sh[tid] += v;
        __syncthreads();
    }
    if (i < N) {
        int excl = bpref + sh[tid] - own;
        g_rowptr[i] = excl;
        g_cnt[i]    = excl;                       // scatter cursor
        g_dinv[i]   = rsqrtf((float)own + 1.0f);
        if (i == N - 1) g_rowptr[N] = excl + own;
    }
}

// -------- 5) scatter edges into CSR with precomputed source weight --------
__global__ void scatter_k(const void* ei, int E) {
    int e = blockIdx.x * blockDim.x + threadIdx.x;
    if (e >= E) return;
    int src, dst;
    if (g_is64) {
        src = (int)((const long long*)ei)[e];
        dst = (int)((const long long*)ei)[(size_t)E + e];
    } else {
        src = ((const int*)ei)[e];
        dst = ((const int*)ei)[(size_t)E + e];
    }
    int pos = atomicAdd(&g_cnt[dst], 1);
    g_cw[pos] = make_int2(src, __float_as_int(g_dinv[src]));
}

// -------- gather-accumulate core: fp16 rows, fp32 accumulation --------
__device__ __forceinline__ float4 hop_row(const uint2* __restrict__ tab,
                                          int gw, int lane) {
    int beg = g_rowptr[gw], end = g_rowptr[gw + 1];
    float4 acc = make_float4(0.f, 0.f, 0.f, 0.f);
    for (int j = beg; j < end; j += 32) {
        int2 cw = make_int2(0, 0);
        if (j + lane < end) cw = g_cw[j + lane];
        int cnt = min(32, end - j);
        int k = 0;
        for (; k + 1 < cnt; k += 2) {
            int   s0 = __shfl_sync(0xffffffffu, cw.x, k);
            float w0 = __int_as_float(__shfl_sync(0xffffffffu, cw.y, k));
            int   s1 = __shfl_sync(0xffffffffu, cw.x, k + 1);
            float w1 = __int_as_float(__shfl_sync(0xffffffffu, cw.y, k + 1));
            uint2 u0 = tab[(size_t)s0 * 32 + lane];
            uint2 u1 = tab[(size_t)s1 * 32 + lane];
            float2 a0 = __half22float2(*(const __half2*)&u0.x);
            float2 b0 = __half22float2(*(const __half2*)&u0.y);
            float2 a1 = __half22float2(*(const __half2*)&u1.x);
            float2 b1 = __half22float2(*(const __half2*)&u1.y);
            acc.x = fmaf(w0, a0.x, fmaf(w1, a1.x, acc.x));
            acc.y = fmaf(w0, a0.y, fmaf(w1, a1.y, acc.y));
            acc.z = fmaf(w0, b0.x, fmaf(w1, b1.x, acc.z));
            acc.w = fmaf(w0, b0.y, fmaf(w1, b1.y, acc.w));
        }
        if (k < cnt) {
            int   s0 = __shfl_sync(0xffffffffu, cw.x, k);
            float w0 = __int_as_float(__shfl_sync(0xffffffffu, cw.y, k));
            uint2 u0 = tab[(size_t)s0 * 32 + lane];
            float2 a0 = __half22float2(*(const __half2*)&u0.x);
            float2 b0 = __half22float2(*(const __half2*)&u0.y);
            acc.x = fmaf(w0, a0.x, acc.x);
            acc.y = fmaf(w0, a0.y, acc.y);
            acc.z = fmaf(w0, b0.x, acc.z);
            acc.w = fmaf(w0, b0.y, acc.w);
        }
    }
    // self loop: dinv^2 * own row
    float  di = g_dinv[gw];
    uint2  u  = tab[(size_t)gw * 32 + lane];
    float2 a  = __half22float2(*(const __half2*)&u.x);
    float2 b  = __half22float2(*(const __half2*)&u.y);
    float  sl = di * di;
    acc.x = di * acc.x + sl * a.x;
    acc.y = di * acc.y + sl * a.y;
    acc.z = di * acc.z + sl * b.x;
    acc.w = di * acc.w + sl * b.y;
    return acc;
}

// -------- 6) hop 1 (x_fp16 -> h1_fp16) --------
__global__ void __launch_bounds__(256) hop1_k(int N) {
    int gw   = (blockIdx.x * blockDim.x + threadIdx.x) >> 5;
    int lane = threadIdx.x & 31;
    if (gw >= N) return;
    float4 acc = hop_row(g_xh, gw, lane);
    uint2 o;
    *(__half2*)&o.x = __floats2half2_rn(acc.x, acc.y);
    *(__half2*)&o.y = __floats2half2_rn(acc.z, acc.w);
    g_h1h[(size_t)gw * 32 + lane] = o;
}

// -------- 7) hop 2 fused with linear projection --------
__global__ void __launch_bounds__(256) hop2_gemm_k(const float* __restrict__ W,
                                                   const float* __restrict__ b,
                                                   float* __restrict__ out,
                                                   int N, int C) {
    extern __shared__ float sm[];               // C*F + C floats
    const float4* sW4 = (const float4*)sm;
    float*        sb  = sm + C * F_DIM;
    for (int idx = threadIdx.x; idx < C * F_DIM; idx += blockDim.x) sm[idx] = W[idx];
    for (int idx = threadIdx.x; idx < C; idx += blockDim.x) sb[idx] = b[idx];
    __syncthreads();

    int gw   = (blockIdx.x * blockDim.x + threadIdx.x) >> 5;
    int lane = threadIdx.x & 31;
    if (gw >= N) return;

    float4 acc = hop_row(g_h1h, gw, lane);      // h2 row segment [lane*4 .. lane*4+3]

    float my0 = 0.f, my1 = 0.f;
    for (int c = 0; c < C; c++) {
        float4 wv = sW4[c * 32 + lane];
        float p = acc.x * wv.x + acc.y * wv.y + acc.z * wv.z + acc.w * wv.w;
        p += __shfl_xor_sync(0xffffffffu, p, 16);
        p += __shfl_xor_sync(0xffffffffu, p, 8);
        p += __shfl_xor_sync(0xffffffffu, p, 4);
        p += __shfl_xor_sync(0xffffffffu, p, 2);
        p += __shfl_xor_sync(0xffffffffu, p, 1);
        p += sb[c];
        if (c < 32) { if (lane == c)      my0 = p; }
        else        { if (lane == c - 32) my1 = p; }
    }
    float* orow = out + (size_t)gw * C;
    orow[lane] = my0;
    if (lane < C - 32) orow[32 + lane] = my1;
}

extern "C" void kernel_launch(void* const* d_in, const int* in_sizes, int n_in,
                              void* d_out, int out_size) {
    const float* x  = (const float*)d_in[0];
    const void*  ei = d_in[1];
    const float* W  = (const float*)d_in[2];
    const float* b  = (const float*)d_in[3];

    int C   = in_sizes[3];                 // 40
    int F   = in_sizes[2] / C;             // 128
    int N   = in_sizes[0] / F;             // 100000
    int E   = in_sizes[1] / 2;             // 1600000
    int NB  = (N + 1023) / 1024;
    int NF2 = N * F / 2;

    prep_k<<<1184, 256>>>((const float2*)x, ei, N, NF2);
    hist_k<<<(E + 255) / 256, 256>>>(ei, E);
    scan1_k<<<NB, 256>>>(N);
    scan3_k<<<NB, 1024>>>(N);
    scatter_k<<<(E + 255) / 256, 256>>>(ei, E);

    int blocks = (N * 32 + 255) / 256;     // warp per node
    hop1_k<<<blocks, 256>>>(N);
    size_t shmem = (size_t)(C * F + C) * sizeof(float);
    hop2_gemm_k<<<blocks, 256, shmem>>>(W, b, (float*)d_out, N, C);
}